// round 11
// baseline (speedup 1.0000x reference)
#include <cuda_runtime.h>
#include <cstdint>

// Problem dims
#define T_STEPS 256
#define BATCH   128
#define INDIM   1024
#define HID     1024
#define OUTDIM  256
#define MROWS   (T_STEPS * BATCH)   // 32768
#define BETA_F  0.9f
#define KC      512                 // Eigen gebp panel depth (bit-exactness contract)

// Scratch (allocation-free rule: __device__ globals)
__device__ float g_cur1[(size_t)MROWS * HID];     // 128 MB
__device__ float g_cur2[(size_t)MROWS * OUTDIM];  // 32 MB
__device__ float g_xT  [(size_t)INDIM * MROWS];   // 128 MB  x transposed (k-major)
__device__ float g_w1T [(size_t)INDIM * HID];     // 4 MB    w1 transposed
__device__ float g_w2T [(size_t)HID * OUTDIM];    // 1 MB    w2 transposed

typedef unsigned long long ull;

// ---- packed f32x2 helpers (each lane = independent IEEE fp32 rn op) --------
__device__ __forceinline__ void ffma2(ull& d, ull a, ull b) {
    asm("fma.rn.f32x2 %0, %1, %2, %0;" : "+l"(d) : "l"(a), "l"(b));
}
__device__ __forceinline__ ull bcast2(float x) {
    ull r; asm("mov.b64 %0, {%1, %1};" : "=l"(r) : "f"(x)); return r;
}
__device__ __forceinline__ void unpack2(float& lo, float& hi, ull v) {
    asm("mov.b64 {%0, %1}, %2;" : "=f"(lo), "=f"(hi) : "l"(v));
}

// ---- cp.async helpers ------------------------------------------------------
__device__ __forceinline__ void cp_async16(uint32_t smem, const void* g) {
    asm volatile("cp.async.cg.shared.global [%0], [%1], 16;" :: "r"(smem), "l"(g));
}
__device__ __forceinline__ void cp_commit() {
    asm volatile("cp.async.commit_group;" ::: "memory");
}
template<int N>
__device__ __forceinline__ void cp_wait() {
    asm volatile("cp.async.wait_group %0;" :: "n"(N) : "memory");
}

// ---------------------------------------------------------------------------
// Tiled transpose: in [rows][cols] -> out [cols][rows]. Pure bit copy.
// ---------------------------------------------------------------------------
__global__ void transpose32(const float* __restrict__ in, float* __restrict__ out,
                            int rows, int cols)
{
    __shared__ float tile[32][33];
    const int c0 = blockIdx.x * 32;
    const int r0 = blockIdx.y * 32;
    #pragma unroll
    for (int j = 0; j < 32; j += 8)
        tile[threadIdx.y + j][threadIdx.x] =
            in[(size_t)(r0 + threadIdx.y + j) * cols + c0 + threadIdx.x];
    __syncthreads();
    #pragma unroll
    for (int j = 0; j < 32; j += 8)
        out[(size_t)(c0 + threadIdx.y + j) * rows + r0 + threadIdx.x] =
            tile[threadIdx.x][threadIdx.y + j];
}

// ---------------------------------------------------------------------------
// GEMM1 panel (kc=512): A,B both k-major, pure cp.async, 2-stage, BK=32.
// Numerics contract (bit-match Eigen gebp kc=512, VERIFIED rel_err==0):
//   per element: S = fadd( chain(k=0..511), chain(k=512..1023) ), chains are
//   ascending-k fp32 FMA chains from 0; then ONE rounded bias add (phase 1).
// Tile 128x128x32, 256 threads, microtile 8m(4 f32x2 m-pairs) x 8n.
// ---------------------------------------------------------------------------
#define BM 128
#define BN 128
#define BK 32
#define NITER (KC / BK)   // 16

__global__ __launch_bounds__(256, 2)
void sgemm1_panel(const float* __restrict__ A,
                  const float* __restrict__ B,
                  const float* __restrict__ bias,
                  float* __restrict__ C,
                  int lda, int ldb, int N, int addBias)
{
    __shared__ __align__(16) float As[2][BK][BM];
    __shared__ __align__(16) float Bs[2][BK][BN];

    const int tid = threadIdx.x;
    const int bm = blockIdx.y * BM;
    const int bn = blockIdx.x * BN;

    const int tx = (tid & 15) << 2;   // n base (4 wide); second group at +64
    const int ty = (tid >> 4) << 2;   // m base (4 tall); second group at +64

    const int lk  = tid >> 5;          // 0..7
    const int lof = (tid & 31) << 2;   // 0..124

    const uint32_t sA = (uint32_t)__cvta_generic_to_shared(&As[0][0][0]);
    const uint32_t sB = (uint32_t)__cvta_generic_to_shared(&Bs[0][0][0]);
    #define SA_ADDR(b, k, off) (sA + (uint32_t)(((b) * BK + (k)) * BM + (off)) * 4u)
    #define SB_ADDR(b, k, off) (sB + (uint32_t)(((b) * BK + (k)) * BN + (off)) * 4u)

    ull acc[4][8];
    #pragma unroll
    for (int i = 0; i < 4; i++)
        #pragma unroll
        for (int j = 0; j < 8; j++) acc[i][j] = 0ull;

    // prologue
    #pragma unroll
    for (int r = 0; r < BK; r += 8) {
        cp_async16(SB_ADDR(0, lk + r, lof), &B[(size_t)(lk + r) * ldb + bn + lof]);
        cp_async16(SA_ADDR(0, lk + r, lof), &A[(size_t)(lk + r) * lda + bm + lof]);
    }
    cp_commit();
    cp_wait<0>();
    __syncthreads();

    int buf = 0;
    for (int iter = 0; iter < NITER; iter++) {
        if (iter + 1 < NITER) {
            const int kt = (iter + 1) * BK;
            const int nb = buf ^ 1;
            #pragma unroll
            for (int r = 0; r < BK; r += 8) {
                cp_async16(SB_ADDR(nb, lk + r, lof), &B[(size_t)(kt + lk + r) * ldb + bn + lof]);
                cp_async16(SA_ADDR(nb, lk + r, lof), &A[(size_t)(kt + lk + r) * lda + bm + lof]);
            }
            cp_commit();
        }

        #pragma unroll
        for (int k = 0; k < BK; k++) {
            ulonglong2 av0 = *reinterpret_cast<const ulonglong2*>(&As[buf][k][ty]);
            ulonglong2 av1 = *reinterpret_cast<const ulonglong2*>(&As[buf][k][ty + 64]);
            float4 b0 = *reinterpret_cast<const float4*>(&Bs[buf][k][tx]);
            float4 b1 = *reinterpret_cast<const float4*>(&Bs[buf][k][tx + 64]);
            ull ap[4] = {av0.x, av0.y, av1.x, av1.y};
            ull bb[8];
            bb[0] = bcast2(b0.x); bb[1] = bcast2(b0.y);
            bb[2] = bcast2(b0.z); bb[3] = bcast2(b0.w);
            bb[4] = bcast2(b1.x); bb[5] = bcast2(b1.y);
            bb[6] = bcast2(b1.z); bb[7] = bcast2(b1.w);
            #pragma unroll
            for (int i = 0; i < 4; i++)
                #pragma unroll
                for (int j = 0; j < 8; j++)
                    ffma2(acc[i][j], ap[i], bb[j]);
        }

        if (iter + 1 < NITER) {
            cp_wait<0>();
            __syncthreads();
            buf ^= 1;
        }
    }

    // epilogue
    if (addBias) {
        float4 bv0 = *reinterpret_cast<const float4*>(&bias[bn + tx]);
        float4 bv1 = *reinterpret_cast<const float4*>(&bias[bn + tx + 64]);
        const float bb[8] = {bv0.x, bv0.y, bv0.z, bv0.w, bv1.x, bv1.y, bv1.z, bv1.w};
        #pragma unroll
        for (int i = 0; i < 4; i++) {
            int r0 = bm + ((i < 2) ? (ty + 2 * i) : (ty + 64 + 2 * (i - 2)));
            #pragma unroll
            for (int half = 0; half < 2; half++) {
                int row = r0 + half;
                float4 p0 = *reinterpret_cast<const float4*>(&C[(size_t)row * N + bn + tx]);
                float4 p1 = *reinterpret_cast<const float4*>(&C[(size_t)row * N + bn + tx + 64]);
                float pr[8] = {p0.x, p0.y, p0.z, p0.w, p1.x, p1.y, p1.z, p1.w};
                float o[8];
                #pragma unroll
                for (int j = 0; j < 8; j++) {
                    float lo, hi;
                    unpack2(lo, hi, acc[i][j]);
                    float mine = half ? hi : lo;
                    o[j] = __fadd_rn(__fadd_rn(pr[j], mine), bb[j]);
                }
                float4 s0 = {o[0], o[1], o[2], o[3]};
                float4 s1 = {o[4], o[5], o[6], o[7]};
                *reinterpret_cast<float4*>(&C[(size_t)row * N + bn + tx]) = s0;
                *reinterpret_cast<float4*>(&C[(size_t)row * N + bn + tx + 64]) = s1;
            }
        }
    } else {
        #pragma unroll
        for (int i = 0; i < 4; i++) {
            int r0 = bm + ((i < 2) ? (ty + 2 * i) : (ty + 64 + 2 * (i - 2)));
            float lo[8], hi[8];
            #pragma unroll
            for (int j = 0; j < 8; j++) unpack2(lo[j], hi[j], acc[i][j]);
            float4 s0 = {lo[0], lo[1], lo[2], lo[3]};
            float4 s1 = {lo[4], lo[5], lo[6], lo[7]};
            float4 s2 = {hi[0], hi[1], hi[2], hi[3]};
            float4 s3 = {hi[4], hi[5], hi[6], hi[7]};
            *reinterpret_cast<float4*>(&C[(size_t)r0 * N + bn + tx]) = s0;
            *reinterpret_cast<float4*>(&C[(size_t)r0 * N + bn + tx + 64]) = s1;
            *reinterpret_cast<float4*>(&C[(size_t)(r0 + 1) * N + bn + tx]) = s2;
            *reinterpret_cast<float4*>(&C[(size_t)(r0 + 1) * N + bn + tx + 64]) = s3;
        }
    }
    #undef SA_ADDR
    #undef SB_ADDR
}

// ---------------------------------------------------------------------------
// GEMM2 panel: BN2=64 for wave fill (1024 CTAs), A m-major (spk1, LDG+STS
// staged), B k-major (w2T, cp.async). Same per-element numerics contract.
// Tile 128x64x32, 256 threads, microtile 8m(4 m-pairs) x 4n.
// ---------------------------------------------------------------------------
#define BN2 64

__global__ __launch_bounds__(256, 2)
void sgemm2_panel(const float* __restrict__ A,
                  const float* __restrict__ B,
                  const float* __restrict__ bias,
                  float* __restrict__ C,
                  int lda, int ldb, int N, int addBias)
{
    __shared__ __align__(16) float As[2][BK][BM];
    __shared__ __align__(16) float Bs[2][BK][BN2];

    const int tid = threadIdx.x;
    const int bm = blockIdx.y * BM;
    const int bn = blockIdx.x * BN2;

    const int tx = (tid & 15) << 2;   // n base (4 wide), covers all 64
    const int ty = (tid >> 4) << 2;   // m base (4 tall); second group at +64

    // B cp.async: 32x64 tile = 512 chunks; rows lkB, lkB+16; col lofB
    const int lkB  = tid >> 4;         // 0..15
    const int lofB = (tid & 15) << 2;  // 0..60

    // A staging: rows lr, lr+64; 8 k-cols each (2 float4)
    const int lr  = tid >> 2;          // 0..63
    const int lc8 = (tid & 3) << 3;    // 0,8,16,24

    const uint32_t sB = (uint32_t)__cvta_generic_to_shared(&Bs[0][0][0]);
    #define SB2_ADDR(b, k, off) (sB + (uint32_t)(((b) * BK + (k)) * BN2 + (off)) * 4u)

    ull acc[4][4];
    #pragma unroll
    for (int i = 0; i < 4; i++)
        #pragma unroll
        for (int j = 0; j < 4; j++) acc[i][j] = 0ull;

    // prologue
    cp_async16(SB2_ADDR(0, lkB, lofB),      &B[(size_t)lkB * ldb + bn + lofB]);
    cp_async16(SB2_ADDR(0, lkB + 16, lofB), &B[(size_t)(lkB + 16) * ldb + bn + lofB]);
    #pragma unroll
    for (int h = 0; h < 2; h++) {
        const int row = lr + h * 64;
        float4 a0 = *reinterpret_cast<const float4*>(&A[(size_t)(bm + row) * lda + lc8]);
        float4 a1 = *reinterpret_cast<const float4*>(&A[(size_t)(bm + row) * lda + lc8 + 4]);
        As[0][lc8 + 0][row] = a0.x; As[0][lc8 + 1][row] = a0.y;
        As[0][lc8 + 2][row] = a0.z; As[0][lc8 + 3][row] = a0.w;
        As[0][lc8 + 4][row] = a1.x; As[0][lc8 + 5][row] = a1.y;
        As[0][lc8 + 6][row] = a1.z; As[0][lc8 + 7][row] = a1.w;
    }
    cp_commit();
    cp_wait<0>();
    __syncthreads();

    int buf = 0;
    for (int iter = 0; iter < NITER; iter++) {
        float4 stA[4];
        if (iter + 1 < NITER) {
            const int kt = (iter + 1) * BK;
            const int nb = buf ^ 1;
            cp_async16(SB2_ADDR(nb, lkB, lofB),      &B[(size_t)(kt + lkB) * ldb + bn + lofB]);
            cp_async16(SB2_ADDR(nb, lkB + 16, lofB), &B[(size_t)(kt + lkB + 16) * ldb + bn + lofB]);
            stA[0] = *reinterpret_cast<const float4*>(&A[(size_t)(bm + lr) * lda + kt + lc8]);
            stA[1] = *reinterpret_cast<const float4*>(&A[(size_t)(bm + lr) * lda + kt + lc8 + 4]);
            stA[2] = *reinterpret_cast<const float4*>(&A[(size_t)(bm + lr + 64) * lda + kt + lc8]);
            stA[3] = *reinterpret_cast<const float4*>(&A[(size_t)(bm + lr + 64) * lda + kt + lc8 + 4]);
            cp_commit();
        }

        #pragma unroll
        for (int k = 0; k < BK; k++) {
            ulonglong2 av0 = *reinterpret_cast<const ulonglong2*>(&As[buf][k][ty]);
            ulonglong2 av1 = *reinterpret_cast<const ulonglong2*>(&As[buf][k][ty + 64]);
            float4 b0 = *reinterpret_cast<const float4*>(&Bs[buf][k][tx]);
            ull ap[4] = {av0.x, av0.y, av1.x, av1.y};
            ull bb[4];
            bb[0] = bcast2(b0.x); bb[1] = bcast2(b0.y);
            bb[2] = bcast2(b0.z); bb[3] = bcast2(b0.w);
            #pragma unroll
            for (int i = 0; i < 4; i++)
                #pragma unroll
                for (int j = 0; j < 4; j++)
                    ffma2(acc[i][j], ap[i], bb[j]);
        }

        if (iter + 1 < NITER) {
            const int nb = buf ^ 1;
            const int row0 = lr, row1 = lr + 64;
            As[nb][lc8 + 0][row0] = stA[0].x; As[nb][lc8 + 1][row0] = stA[0].y;
            As[nb][lc8 + 2][row0] = stA[0].z; As[nb][lc8 + 3][row0] = stA[0].w;
            As[nb][lc8 + 4][row0] = stA[1].x; As[nb][lc8 + 5][row0] = stA[1].y;
            As[nb][lc8 + 6][row0] = stA[1].z; As[nb][lc8 + 7][row0] = stA[1].w;
            As[nb][lc8 + 0][row1] = stA[2].x; As[nb][lc8 + 1][row1] = stA[2].y;
            As[nb][lc8 + 2][row1] = stA[2].z; As[nb][lc8 + 3][row1] = stA[2].w;
            As[nb][lc8 + 4][row1] = stA[3].x; As[nb][lc8 + 5][row1] = stA[3].y;
            As[nb][lc8 + 6][row1] = stA[3].z; As[nb][lc8 + 7][row1] = stA[3].w;
            cp_wait<0>();
            __syncthreads();
            buf = nb;
        }
    }

    // epilogue
    if (addBias) {
        float4 bv = *reinterpret_cast<const float4*>(&bias[bn + tx]);
        const float bb[4] = {bv.x, bv.y, bv.z, bv.w};
        #pragma unroll
        for (int i = 0; i < 4; i++) {
            int r0 = bm + ((i < 2) ? (ty + 2 * i) : (ty + 64 + 2 * (i - 2)));
            #pragma unroll
            for (int half = 0; half < 2; half++) {
                int row = r0 + half;
                float4 p0 = *reinterpret_cast<const float4*>(&C[(size_t)row * N + bn + tx]);
                float pr[4] = {p0.x, p0.y, p0.z, p0.w};
                float o[4];
                #pragma unroll
                for (int j = 0; j < 4; j++) {
                    float lo, hi;
                    unpack2(lo, hi, acc[i][j]);
                    float mine = half ? hi : lo;
                    o[j] = __fadd_rn(__fadd_rn(pr[j], mine), bb[j]);
                }
                float4 s0 = {o[0], o[1], o[2], o[3]};
                *reinterpret_cast<float4*>(&C[(size_t)row * N + bn + tx]) = s0;
            }
        }
    } else {
        #pragma unroll
        for (int i = 0; i < 4; i++) {
            int r0 = bm + ((i < 2) ? (ty + 2 * i) : (ty + 64 + 2 * (i - 2)));
            float lo[4], hi[4];
            #pragma unroll
            for (int j = 0; j < 4; j++) unpack2(lo[j], hi[j], acc[i][j]);
            float4 s0 = {lo[0], lo[1], lo[2], lo[3]};
            float4 s1 = {hi[0], hi[1], hi[2], hi[3]};
            *reinterpret_cast<float4*>(&C[(size_t)r0 * N + bn + tx]) = s0;
            *reinterpret_cast<float4*>(&C[(size_t)(r0 + 1) * N + bn + tx]) = s1;
        }
    }
    #undef SB2_ADDR
}

// ---------------------------------------------------------------------------
// LIF recurrence, XLA-exact op ordering per lane (no FMA contraction).
// Blocked prefetch: 4 independent LDGs in flight (MLP=4) on the serial scan.
// ---------------------------------------------------------------------------
__device__ __forceinline__ void lif_step(float& mem, float& s, float c, float thr) {
    float t0 = __fmul_rn(BETA_F, mem);
    float t1 = __fadd_rn(t0, c);
    float t2 = __fmul_rn(s, thr);
    mem = __fsub_rn(t1, t2);
    s = (__fsub_rn(mem, thr) > 0.f) ? 1.0f : 0.0f;
}

__global__ void lif_scan1(const float* __restrict__ cur,
                          const float* __restrict__ thr_p,
                          float* __restrict__ spk_rec,
                          int stride)
{
    const int idx = blockIdx.x * blockDim.x + threadIdx.x;
    const float thr = *thr_p;
    float mem = 0.f, s = 0.f;
    const float* p = cur + idx;
    float* q = spk_rec + idx;

    float cb[4];
    #pragma unroll
    for (int i = 0; i < 4; i++) cb[i] = p[(size_t)i * stride];

    for (int t = 0; t < T_STEPS; t += 4) {
        float nb[4];
        #pragma unroll
        for (int i = 0; i < 4; i++) {
            int tt = t + 4 + i;
            nb[i] = (tt < T_STEPS) ? p[(size_t)tt * stride] : 0.f;
        }
        #pragma unroll
        for (int i = 0; i < 4; i++) {
            lif_step(mem, s, cb[i], thr);
            q[(size_t)(t + i) * stride] = s;
        }
        #pragma unroll
        for (int i = 0; i < 4; i++) cb[i] = nb[i];
    }
}

// ---------------------------------------------------------------------------
extern "C" void kernel_launch(void* const* d_in, const int* in_sizes, int n_in,
                              void* d_out, int out_size)
{
    const float* x    = (const float*)d_in[0];  // [T,B,I]
    const float* w1   = (const float*)d_in[1];  // [H,I]
    const float* b1   = (const float*)d_in[2];  // [H]
    const float* w2   = (const float*)d_in[3];  // [O,H]
    const float* b2   = (const float*)d_in[4];  // [O]
    const float* thr1 = (const float*)d_in[5];  // scalar
    const float* thr2 = (const float*)d_in[6];  // scalar

    float* out  = (float*)d_out;
    float* spk1 = out;                                    // [T,B,H]
    float* spk2 = out + (size_t)T_STEPS * BATCH * HID;    // [T,B,O]

    float *cur1, *cur2, *xT, *w1T, *w2T;
    cudaGetSymbolAddress((void**)&cur1, g_cur1);
    cudaGetSymbolAddress((void**)&cur2, g_cur2);
    cudaGetSymbolAddress((void**)&xT,  g_xT);
    cudaGetSymbolAddress((void**)&w1T, g_w1T);
    cudaGetSymbolAddress((void**)&w2T, g_w2T);

    // prep: bit-copy transposes to k-major layouts (launch idx 0-2;
    // GEMM1 phase0 lands at idx 3 = the ncu capture slot)
    transpose32<<<dim3(INDIM / 32, MROWS / 32), dim3(32, 8)>>>(x, xT, MROWS, INDIM);
    transpose32<<<dim3(INDIM / 32, HID / 32), dim3(32, 8)>>>(w1, w1T, HID, INDIM);
    transpose32<<<dim3(HID / 32, OUTDIM / 32), dim3(32, 8)>>>(w2, w2T, OUTDIM, HID);

    // 1) cur1 = X @ W1^T + b1   (two kc=512 panels; k-major cp.async)
    {
        dim3 grid(HID / BN, MROWS / BM);
        sgemm1_panel<<<grid, 256>>>(xT, w1T, b1, cur1, MROWS, HID, HID, 0);
        sgemm1_panel<<<grid, 256>>>(xT + (size_t)KC * MROWS, w1T + (size_t)KC * HID,
                                    b1, cur1, MROWS, HID, HID, 1);
    }
    // 2) LIF layer 1 -> spk1_rec
    lif_scan1<<<(BATCH * HID) / 256, 256>>>(cur1, thr1, spk1, BATCH * HID);

    // 3) cur2 = spk1_rec @ W2^T + b2   (BN2=64: 1024 CTAs for wave fill)
    {
        dim3 grid(OUTDIM / BN2, MROWS / BM);
        sgemm2_panel<<<grid, 256>>>(spk1, w2T, b2, cur2, HID, OUTDIM, OUTDIM, 0);
        sgemm2_panel<<<grid, 256>>>(spk1 + KC, w2T + (size_t)KC * OUTDIM,
                                    b2, cur2, HID, OUTDIM, OUTDIM, 1);
    }
    // 4) LIF layer 2 -> spk2_rec
    lif_scan1<<<(BATCH * OUTDIM) / 256, 256>>>(cur2, thr2, spk2, BATCH * OUTDIM);
}

// round 12
// speedup vs baseline: 1.0033x; 1.0033x over previous
#include <cuda_runtime.h>
#include <cstdint>

// Problem dims
#define T_STEPS 256
#define BATCH   128
#define INDIM   1024
#define HID     1024
#define OUTDIM  256
#define MROWS   (T_STEPS * BATCH)   // 32768
#define BETA_F  0.9f
#define KC      512                 // Eigen gebp panel depth (bit-exactness contract)

// Scratch (allocation-free rule: __device__ globals)
__device__ float g_cur1[(size_t)MROWS * HID];     // 128 MB
__device__ float g_cur2[(size_t)MROWS * OUTDIM];  // 32 MB
__device__ float g_xT  [(size_t)INDIM * MROWS];   // 128 MB  x transposed (k-major)
__device__ float g_w1T [(size_t)INDIM * HID];     // 4 MB    w1 transposed
__device__ float g_w2T [(size_t)HID * OUTDIM];    // 1 MB    w2 transposed

typedef unsigned long long ull;

// ---- packed f32x2 helpers (each lane = independent IEEE fp32 rn op) --------
__device__ __forceinline__ void ffma2(ull& d, ull a, ull b) {
    asm("fma.rn.f32x2 %0, %1, %2, %0;" : "+l"(d) : "l"(a), "l"(b));
}
__device__ __forceinline__ void fadd2(ull& d, ull a) {
    asm("add.rn.f32x2 %0, %0, %1;" : "+l"(d) : "l"(a));
}
__device__ __forceinline__ ull bcast2(float x) {
    ull r; asm("mov.b64 %0, {%1, %1};" : "=l"(r) : "f"(x)); return r;
}
__device__ __forceinline__ void unpack2(float& lo, float& hi, ull v) {
    asm("mov.b64 {%0, %1}, %2;" : "=f"(lo), "=f"(hi) : "l"(v));
}

// ---- cp.async helpers ------------------------------------------------------
__device__ __forceinline__ void cp_async16(uint32_t smem, const void* g) {
    asm volatile("cp.async.cg.shared.global [%0], [%1], 16;" :: "r"(smem), "l"(g));
}
__device__ __forceinline__ void cp_commit() {
    asm volatile("cp.async.commit_group;" ::: "memory");
}
template<int N>
__device__ __forceinline__ void cp_wait() {
    asm volatile("cp.async.wait_group %0;" :: "n"(N) : "memory");
}

// ---------------------------------------------------------------------------
// Tiled transpose: in [rows][cols] -> out [cols][rows]. Pure bit copy.
// ---------------------------------------------------------------------------
__global__ void transpose32(const float* __restrict__ in, float* __restrict__ out,
                            int rows, int cols)
{
    __shared__ float tile[32][33];
    const int c0 = blockIdx.x * 32;
    const int r0 = blockIdx.y * 32;
    #pragma unroll
    for (int j = 0; j < 32; j += 8)
        tile[threadIdx.y + j][threadIdx.x] =
            in[(size_t)(r0 + threadIdx.y + j) * cols + c0 + threadIdx.x];
    __syncthreads();
    #pragma unroll
    for (int j = 0; j < 32; j += 8)
        out[(size_t)(c0 + threadIdx.y + j) * rows + r0 + threadIdx.x] =
            tile[threadIdx.x][threadIdx.y + j];
}

// ---------------------------------------------------------------------------
// GEMM1 panel (kc=512): A,B both k-major, pure cp.async, 2-stage, BK=32.
// (EXACT R10 config: GEMM1-phase0 measured 530 us, fma=81.4%.)
// Numerics contract (bit-match Eigen gebp kc=512, VERIFIED rel_err==0):
//   per element: S = fadd( chain(k=0..511), chain(k=512..1023) ), chains are
//   ascending-k fp32 FMA chains from 0; then ONE rounded bias add (phase 1).
// Tile 128x128x32, 256 threads, microtile 8m(4 f32x2 m-pairs) x 8n.
// ---------------------------------------------------------------------------
#define BM 128
#define BN 128
#define BK 32
#define NITER (KC / BK)   // 16

__global__ __launch_bounds__(256, 2)
void sgemm1_panel(const float* __restrict__ A,
                  const float* __restrict__ B,
                  const float* __restrict__ bias,
                  float* __restrict__ C,
                  int lda, int ldb, int N, int addBias)
{
    __shared__ __align__(16) float As[2][BK][BM];
    __shared__ __align__(16) float Bs[2][BK][BN];

    const int tid = threadIdx.x;
    const int bm = blockIdx.y * BM;
    const int bn = blockIdx.x * BN;

    const int tx = (tid & 15) << 2;   // n base (4 wide); second group at +64
    const int ty = (tid >> 4) << 2;   // m base (4 tall); second group at +64

    const int lk  = tid >> 5;          // 0..7
    const int lof = (tid & 31) << 2;   // 0..124

    const uint32_t sA = (uint32_t)__cvta_generic_to_shared(&As[0][0][0]);
    const uint32_t sB = (uint32_t)__cvta_generic_to_shared(&Bs[0][0][0]);
    #define SA_ADDR(b, k, off) (sA + (uint32_t)(((b) * BK + (k)) * BM + (off)) * 4u)
    #define SB_ADDR(b, k, off) (sB + (uint32_t)(((b) * BK + (k)) * BN + (off)) * 4u)

    ull acc[4][8];
    #pragma unroll
    for (int i = 0; i < 4; i++)
        #pragma unroll
        for (int j = 0; j < 8; j++) acc[i][j] = 0ull;

    // prologue
    #pragma unroll
    for (int r = 0; r < BK; r += 8) {
        cp_async16(SB_ADDR(0, lk + r, lof), &B[(size_t)(lk + r) * ldb + bn + lof]);
        cp_async16(SA_ADDR(0, lk + r, lof), &A[(size_t)(lk + r) * lda + bm + lof]);
    }
    cp_commit();
    cp_wait<0>();
    __syncthreads();

    int buf = 0;
    for (int iter = 0; iter < NITER; iter++) {
        if (iter + 1 < NITER) {
            const int kt = (iter + 1) * BK;
            const int nb = buf ^ 1;
            #pragma unroll
            for (int r = 0; r < BK; r += 8) {
                cp_async16(SB_ADDR(nb, lk + r, lof), &B[(size_t)(kt + lk + r) * ldb + bn + lof]);
                cp_async16(SA_ADDR(nb, lk + r, lof), &A[(size_t)(kt + lk + r) * lda + bm + lof]);
            }
            cp_commit();
        }

        #pragma unroll
        for (int k = 0; k < BK; k++) {
            ulonglong2 av0 = *reinterpret_cast<const ulonglong2*>(&As[buf][k][ty]);
            ulonglong2 av1 = *reinterpret_cast<const ulonglong2*>(&As[buf][k][ty + 64]);
            float4 b0 = *reinterpret_cast<const float4*>(&Bs[buf][k][tx]);
            float4 b1 = *reinterpret_cast<const float4*>(&Bs[buf][k][tx + 64]);
            ull ap[4] = {av0.x, av0.y, av1.x, av1.y};
            ull bb[8];
            bb[0] = bcast2(b0.x); bb[1] = bcast2(b0.y);
            bb[2] = bcast2(b0.z); bb[3] = bcast2(b0.w);
            bb[4] = bcast2(b1.x); bb[5] = bcast2(b1.y);
            bb[6] = bcast2(b1.z); bb[7] = bcast2(b1.w);
            #pragma unroll
            for (int i = 0; i < 4; i++)
                #pragma unroll
                for (int j = 0; j < 8; j++)
                    ffma2(acc[i][j], ap[i], bb[j]);
        }

        if (iter + 1 < NITER) {
            cp_wait<0>();
            __syncthreads();
            buf ^= 1;
        }
    }

    // epilogue
    if (addBias) {
        float4 bv0 = *reinterpret_cast<const float4*>(&bias[bn + tx]);
        float4 bv1 = *reinterpret_cast<const float4*>(&bias[bn + tx + 64]);
        const float bb[8] = {bv0.x, bv0.y, bv0.z, bv0.w, bv1.x, bv1.y, bv1.z, bv1.w};
        #pragma unroll
        for (int i = 0; i < 4; i++) {
            int r0 = bm + ((i < 2) ? (ty + 2 * i) : (ty + 64 + 2 * (i - 2)));
            #pragma unroll
            for (int half = 0; half < 2; half++) {
                int row = r0 + half;
                float4 p0 = *reinterpret_cast<const float4*>(&C[(size_t)row * N + bn + tx]);
                float4 p1 = *reinterpret_cast<const float4*>(&C[(size_t)row * N + bn + tx + 64]);
                float pr[8] = {p0.x, p0.y, p0.z, p0.w, p1.x, p1.y, p1.z, p1.w};
                float o[8];
                #pragma unroll
                for (int j = 0; j < 8; j++) {
                    float lo, hi;
                    unpack2(lo, hi, acc[i][j]);
                    float mine = half ? hi : lo;
                    o[j] = __fadd_rn(__fadd_rn(pr[j], mine), bb[j]);
                }
                float4 s0 = {o[0], o[1], o[2], o[3]};
                float4 s1 = {o[4], o[5], o[6], o[7]};
                *reinterpret_cast<float4*>(&C[(size_t)row * N + bn + tx]) = s0;
                *reinterpret_cast<float4*>(&C[(size_t)row * N + bn + tx + 64]) = s1;
            }
        }
    } else {
        #pragma unroll
        for (int i = 0; i < 4; i++) {
            int r0 = bm + ((i < 2) ? (ty + 2 * i) : (ty + 64 + 2 * (i - 2)));
            float lo[8], hi[8];
            #pragma unroll
            for (int j = 0; j < 8; j++) unpack2(lo[j], hi[j], acc[i][j]);
            float4 s0 = {lo[0], lo[1], lo[2], lo[3]};
            float4 s1 = {lo[4], lo[5], lo[6], lo[7]};
            float4 s2 = {hi[0], hi[1], hi[2], hi[3]};
            float4 s3 = {hi[4], hi[5], hi[6], hi[7]};
            *reinterpret_cast<float4*>(&C[(size_t)r0 * N + bn + tx]) = s0;
            *reinterpret_cast<float4*>(&C[(size_t)r0 * N + bn + tx + 64]) = s1;
            *reinterpret_cast<float4*>(&C[(size_t)(r0 + 1) * N + bn + tx]) = s2;
            *reinterpret_cast<float4*>(&C[(size_t)(r0 + 1) * N + bn + tx + 64]) = s3;
        }
    }
    #undef SA_ADDR
    #undef SB_ADDR
}

// ---------------------------------------------------------------------------
// GEMM2 FUSED full-K: BM2=64 x BN=128, grid (2,512)=1024 CTAs (wave fill),
// both kc=512 panels in one kernel with in-register fold at k=512:
//   sum = fadd( fadd(0, chain1), chain2 )   [fadd(0,x) value-exact; the R4
//   in-kernel fold with this exact shape verified rel_err==0]
// then ONE rounded bias add. A m-major (spk1, LDG+STS staged), B k-major
// (w2T, cp.async). Microtile 4m(2 f32x2 m-pairs) x 8n.
// ---------------------------------------------------------------------------
#define BM2 64
#define NITER2 (INDIM / BK)   // 32 iterations over full K=1024

__global__ __launch_bounds__(256, 2)
void sgemm2_fused(const float* __restrict__ A,
                  const float* __restrict__ B,
                  const float* __restrict__ bias,
                  float* __restrict__ C,
                  int lda, int ldb, int N)
{
    __shared__ __align__(16) float As[2][BK][BM2];
    __shared__ __align__(16) float Bs[2][BK][BN];

    const int tid = threadIdx.x;
    const int bm = blockIdx.y * BM2;
    const int bn = blockIdx.x * BN;

    const int tx = (tid & 15) << 2;   // n base (4 wide); second group at +64
    const int ty = (tid >> 4) << 2;   // m base (4 tall), covers all 64

    // B cp.async: 32x128 tile = 1024 chunks; same scheme as GEMM1 B
    const int lk  = tid >> 5;          // 0..7
    const int lof = (tid & 31) << 2;   // 0..124

    // A staging: 64 rows x 32 k = 2048 floats; thread -> row lr2, 8 k-cols
    const int lr2 = tid >> 2;          // 0..63
    const int lc8 = (tid & 3) << 3;    // 0,8,16,24

    const uint32_t sB = (uint32_t)__cvta_generic_to_shared(&Bs[0][0][0]);
    #define SB2_ADDR(b, k, off) (sB + (uint32_t)(((b) * BK + (k)) * BN + (off)) * 4u)

    ull acc[2][8];   // current-panel chains: 2 m-pairs x 8 n
    ull sum[2][8];   // cross-panel accumulator
    #pragma unroll
    for (int i = 0; i < 2; i++)
        #pragma unroll
        for (int j = 0; j < 8; j++) { acc[i][j] = 0ull; sum[i][j] = 0ull; }

    // prologue: tile 0
    #pragma unroll
    for (int r = 0; r < BK; r += 8)
        cp_async16(SB2_ADDR(0, lk + r, lof), &B[(size_t)(lk + r) * ldb + bn + lof]);
    {
        float4 a0 = *reinterpret_cast<const float4*>(&A[(size_t)(bm + lr2) * lda + lc8]);
        float4 a1 = *reinterpret_cast<const float4*>(&A[(size_t)(bm + lr2) * lda + lc8 + 4]);
        As[0][lc8 + 0][lr2] = a0.x; As[0][lc8 + 1][lr2] = a0.y;
        As[0][lc8 + 2][lr2] = a0.z; As[0][lc8 + 3][lr2] = a0.w;
        As[0][lc8 + 4][lr2] = a1.x; As[0][lc8 + 5][lr2] = a1.y;
        As[0][lc8 + 6][lr2] = a1.z; As[0][lc8 + 7][lr2] = a1.w;
    }
    cp_commit();
    cp_wait<0>();
    __syncthreads();

    int buf = 0;
    for (int iter = 0; iter < NITER2; iter++) {
        float4 stA0, stA1;
        if (iter + 1 < NITER2) {
            const int kt = (iter + 1) * BK;
            const int nb = buf ^ 1;
            #pragma unroll
            for (int r = 0; r < BK; r += 8)
                cp_async16(SB2_ADDR(nb, lk + r, lof), &B[(size_t)(kt + lk + r) * ldb + bn + lof]);
            stA0 = *reinterpret_cast<const float4*>(&A[(size_t)(bm + lr2) * lda + kt + lc8]);
            stA1 = *reinterpret_cast<const float4*>(&A[(size_t)(bm + lr2) * lda + kt + lc8 + 4]);
            cp_commit();
        }

        #pragma unroll
        for (int k = 0; k < BK; k++) {
            ulonglong2 av = *reinterpret_cast<const ulonglong2*>(&As[buf][k][ty]);
            float4 b0 = *reinterpret_cast<const float4*>(&Bs[buf][k][tx]);
            float4 b1 = *reinterpret_cast<const float4*>(&Bs[buf][k][tx + 64]);
            ull ap[2] = {av.x, av.y};
            ull bb[8];
            bb[0] = bcast2(b0.x); bb[1] = bcast2(b0.y);
            bb[2] = bcast2(b0.z); bb[3] = bcast2(b0.w);
            bb[4] = bcast2(b1.x); bb[5] = bcast2(b1.y);
            bb[6] = bcast2(b1.z); bb[7] = bcast2(b1.w);
            #pragma unroll
            for (int i = 0; i < 2; i++)
                #pragma unroll
                for (int j = 0; j < 8; j++)
                    ffma2(acc[i][j], ap[i], bb[j]);
        }

        if (iter + 1 < NITER2) {
            const int nb = buf ^ 1;
            As[nb][lc8 + 0][lr2] = stA0.x; As[nb][lc8 + 1][lr2] = stA0.y;
            As[nb][lc8 + 2][lr2] = stA0.z; As[nb][lc8 + 3][lr2] = stA0.w;
            As[nb][lc8 + 4][lr2] = stA1.x; As[nb][lc8 + 5][lr2] = stA1.y;
            As[nb][lc8 + 6][lr2] = stA1.z; As[nb][lc8 + 7][lr2] = stA1.w;
            cp_wait<0>();
            __syncthreads();
            buf = nb;
        }

        // panel boundary: fold chain into cross-panel sum (ONE rounded add/lane)
        if (((iter + 1) * BK) % KC == 0) {
            #pragma unroll
            for (int i = 0; i < 2; i++)
                #pragma unroll
                for (int j = 0; j < 8; j++) {
                    fadd2(sum[i][j], acc[i][j]);
                    acc[i][j] = 0ull;
                }
        }
    }

    // epilogue: ONE rounded bias add per element, 16B stores
    float4 bv0 = *reinterpret_cast<const float4*>(&bias[bn + tx]);
    float4 bv1 = *reinterpret_cast<const float4*>(&bias[bn + tx + 64]);
    const float bb[8] = {bv0.x, bv0.y, bv0.z, bv0.w, bv1.x, bv1.y, bv1.z, bv1.w};
    #pragma unroll
    for (int i = 0; i < 2; i++) {
        int r0 = bm + ty + 2 * i;
        #pragma unroll
        for (int half = 0; half < 2; half++) {
            int row = r0 + half;
            float o[8];
            #pragma unroll
            for (int j = 0; j < 8; j++) {
                float lo, hi;
                unpack2(lo, hi, sum[i][j]);
                float mine = half ? hi : lo;
                o[j] = __fadd_rn(mine, bb[j]);
            }
            float4 s0 = {o[0], o[1], o[2], o[3]};
            float4 s1 = {o[4], o[5], o[6], o[7]};
            *reinterpret_cast<float4*>(&C[(size_t)row * N + bn + tx]) = s0;
            *reinterpret_cast<float4*>(&C[(size_t)row * N + bn + tx + 64]) = s1;
        }
    }
    #undef SB2_ADDR
}

// ---------------------------------------------------------------------------
// LIF recurrence, XLA-exact op ordering per lane (no FMA contraction).
// Scalar, one neuron per thread, next-t prefetch (R10-proven).
// ---------------------------------------------------------------------------
__device__ __forceinline__ void lif_step(float& mem, float& s, float c, float thr) {
    float t0 = __fmul_rn(BETA_F, mem);
    float t1 = __fadd_rn(t0, c);
    float t2 = __fmul_rn(s, thr);
    mem = __fsub_rn(t1, t2);
    s = (__fsub_rn(mem, thr) > 0.f) ? 1.0f : 0.0f;
}

__global__ void lif_scan1(const float* __restrict__ cur,
                          const float* __restrict__ thr_p,
                          float* __restrict__ spk_rec,
                          int stride)
{
    const int idx = blockIdx.x * blockDim.x + threadIdx.x;
    const float thr = *thr_p;
    float mem = 0.f, s = 0.f;
    const float* p = cur + idx;
    float* q = spk_rec + idx;
    float c = p[0];
    #pragma unroll 8
    for (int t = 0; t < T_STEPS; t++) {
        float cn = 0.f;
        if (t + 1 < T_STEPS) cn = p[(size_t)(t + 1) * stride];
        lif_step(mem, s, c, thr);
        q[(size_t)t * stride] = s;
        c = cn;
    }
}

// ---------------------------------------------------------------------------
extern "C" void kernel_launch(void* const* d_in, const int* in_sizes, int n_in,
                              void* d_out, int out_size)
{
    const float* x    = (const float*)d_in[0];  // [T,B,I]
    const float* w1   = (const float*)d_in[1];  // [H,I]
    const float* b1   = (const float*)d_in[2];  // [H]
    const float* w2   = (const float*)d_in[3];  // [O,H]
    const float* b2   = (const float*)d_in[4];  // [O]
    const float* thr1 = (const float*)d_in[5];  // scalar
    const float* thr2 = (const float*)d_in[6];  // scalar

    float* out  = (float*)d_out;
    float* spk1 = out;                                    // [T,B,H]
    float* spk2 = out + (size_t)T_STEPS * BATCH * HID;    // [T,B,O]

    float *cur1, *cur2, *xT, *w1T, *w2T;
    cudaGetSymbolAddress((void**)&cur1, g_cur1);
    cudaGetSymbolAddress((void**)&cur2, g_cur2);
    cudaGetSymbolAddress((void**)&xT,  g_xT);
    cudaGetSymbolAddress((void**)&w1T, g_w1T);
    cudaGetSymbolAddress((void**)&w2T, g_w2T);

    // prep: bit-copy transposes to k-major layouts (launch idx 0-2;
    // GEMM1 phase0 lands at idx 3 = the ncu capture slot)
    transpose32<<<dim3(INDIM / 32, MROWS / 32), dim3(32, 8)>>>(x, xT, MROWS, INDIM);
    transpose32<<<dim3(INDIM / 32, HID / 32), dim3(32, 8)>>>(w1, w1T, HID, INDIM);
    transpose32<<<dim3(HID / 32, OUTDIM / 32), dim3(32, 8)>>>(w2, w2T, OUTDIM, HID);

    // 1) cur1 = X @ W1^T + b1   (two kc=512 panels; k-major cp.async)
    {
        dim3 grid(HID / BN, MROWS / BM);
        sgemm1_panel<<<grid, 256>>>(xT, w1T, b1, cur1, MROWS, HID, HID, 0);
        sgemm1_panel<<<grid, 256>>>(xT + (size_t)KC * MROWS, w1T + (size_t)KC * HID,
                                    b1, cur1, MROWS, HID, HID, 1);
    }
    // 2) LIF layer 1 -> spk1_rec
    lif_scan1<<<(BATCH * HID) / 256, 256>>>(cur1, thr1, spk1, BATCH * HID);

    // 3) cur2 = spk1_rec @ W2^T + b2  (fused full-K, 1024 CTAs for wave fill)
    {
        dim3 grid(OUTDIM / BN, MROWS / BM2);
        sgemm2_fused<<<grid, 256>>>(spk1, w2T, b2, cur2, HID, OUTDIM, OUTDIM);
    }
    // 4) LIF layer 2 -> spk2_rec
    lif_scan1<<<(BATCH * OUTDIM) / 256, 256>>>(cur2, thr2, spk2, BATCH * OUTDIM);
}

// round 13
// speedup vs baseline: 1.0455x; 1.0421x over previous
#include <cuda_runtime.h>
#include <cstdint>

// Problem dims
#define T_STEPS 256
#define BATCH   128
#define INDIM   1024
#define HID     1024
#define OUTDIM  256
#define MROWS   (T_STEPS * BATCH)   // 32768
#define BETA_F  0.9f
#define KC      512                 // Eigen gebp panel depth (bit-exactness contract)

// Scratch (allocation-free rule: __device__ globals)
__device__ float g_cur1[(size_t)MROWS * HID];     // 128 MB
__device__ float g_cur2[(size_t)MROWS * OUTDIM];  // 32 MB
__device__ float g_xT  [(size_t)INDIM * MROWS];   // 128 MB  x transposed (k-major)
__device__ float g_w1T [(size_t)INDIM * HID];     // 4 MB    w1 transposed
__device__ float g_w2T [(size_t)HID * OUTDIM];    // 1 MB    w2 transposed

typedef unsigned long long ull;

// ---- packed f32x2 helpers (each lane = independent IEEE fp32 rn op) --------
__device__ __forceinline__ void ffma2(ull& d, ull a, ull b) {
    asm("fma.rn.f32x2 %0, %1, %2, %0;" : "+l"(d) : "l"(a), "l"(b));
}
__device__ __forceinline__ ull bcast2(float x) {
    ull r; asm("mov.b64 %0, {%1, %1};" : "=l"(r) : "f"(x)); return r;
}
__device__ __forceinline__ void unpack2(float& lo, float& hi, ull v) {
    asm("mov.b64 {%0, %1}, %2;" : "=f"(lo), "=f"(hi) : "l"(v));
}

// ---- cp.async helpers ------------------------------------------------------
__device__ __forceinline__ void cp_async16(uint32_t smem, const void* g) {
    asm volatile("cp.async.cg.shared.global [%0], [%1], 16;" :: "r"(smem), "l"(g));
}
__device__ __forceinline__ void cp_commit() {
    asm volatile("cp.async.commit_group;" ::: "memory");
}
template<int N>
__device__ __forceinline__ void cp_wait() {
    asm volatile("cp.async.wait_group %0;" :: "n"(N) : "memory");
}

// ---------------------------------------------------------------------------
// Tiled transpose: in [rows][cols] -> out [cols][rows]. Pure bit copy.
// ---------------------------------------------------------------------------
__global__ void transpose32(const float* __restrict__ in, float* __restrict__ out,
                            int rows, int cols)
{
    __shared__ float tile[32][33];
    const int c0 = blockIdx.x * 32;
    const int r0 = blockIdx.y * 32;
    #pragma unroll
    for (int j = 0; j < 32; j += 8)
        tile[threadIdx.y + j][threadIdx.x] =
            in[(size_t)(r0 + threadIdx.y + j) * cols + c0 + threadIdx.x];
    __syncthreads();
    #pragma unroll
    for (int j = 0; j < 32; j += 8)
        out[(size_t)(c0 + threadIdx.y + j) * rows + r0 + threadIdx.x] =
            tile[threadIdx.x][threadIdx.y + j];
}

#define BK 32
#define NITER (KC / BK)   // 16

// ---------------------------------------------------------------------------
// GEMM1 panel (kc=512): A,B k-major, cp.async, 2-stage, BK=32.
// NEW SHAPE: 64x128 tile, 128 threads, 4 CTAs/SM — same per-warp instruction
// mix as the proven 128x128 kernel, but barriers sync only 4 warps and 4
// independent CTAs shadow each other's wait+barrier windows.
// Numerics contract (bit-match Eigen gebp kc=512, VERIFIED rel_err==0):
//   per element: S = fadd( chain(k=0..511), chain(k=512..1023) ), chains are
//   ascending-k fp32 FMA chains from 0; then ONE rounded bias add (phase 1).
// Microtile 8m(4 f32x2 m-pairs) x 8n per thread.
// ---------------------------------------------------------------------------
#define BM1 64
#define BN1 128

__global__ __launch_bounds__(128, 4)
void sgemm1_panel(const float* __restrict__ A,
                  const float* __restrict__ B,
                  const float* __restrict__ bias,
                  float* __restrict__ C,
                  int lda, int ldb, int N, int addBias)
{
    __shared__ __align__(16) float As[2][BK][BM1];   // 16 KB
    __shared__ __align__(16) float Bs[2][BK][BN1];   // 32 KB

    const int tid = threadIdx.x;
    const int bm = blockIdx.y * BM1;
    const int bn = blockIdx.x * BN1;

    // compute indexing: 16 thread-cols x 8 thread-rows
    const int tx = (tid & 15) << 2;   // n base (4 wide); second group at +64
    const int ty = (tid >> 4) << 3;   // m base (8 tall, consecutive)

    // A cp.async: 32x64 tile = 8 KB; thread -> row lkA (+8,+16,+24), col lofA
    const int lkA  = tid >> 4;          // 0..7
    const int lofA = (tid & 15) << 2;   // 0..60
    // B cp.async: 32x128 tile = 16 KB; thread -> row lkB (+4,...), col lofB
    const int lkB  = tid >> 5;          // 0..3
    const int lofB = (tid & 31) << 2;   // 0..124

    const uint32_t sA = (uint32_t)__cvta_generic_to_shared(&As[0][0][0]);
    const uint32_t sB = (uint32_t)__cvta_generic_to_shared(&Bs[0][0][0]);
    #define SA_ADDR(b, k, off) (sA + (uint32_t)(((b) * BK + (k)) * BM1 + (off)) * 4u)
    #define SB_ADDR(b, k, off) (sB + (uint32_t)(((b) * BK + (k)) * BN1 + (off)) * 4u)

    ull acc[4][8];   // 4 m-pairs x 8 n
    #pragma unroll
    for (int i = 0; i < 4; i++)
        #pragma unroll
        for (int j = 0; j < 8; j++) acc[i][j] = 0ull;

    // prologue: tile 0 into buffer 0
    #pragma unroll
    for (int r = 0; r < BK; r += 8)
        cp_async16(SA_ADDR(0, lkA + r, lofA), &A[(size_t)(lkA + r) * lda + bm + lofA]);
    #pragma unroll
    for (int r = 0; r < BK; r += 4)
        cp_async16(SB_ADDR(0, lkB + r, lofB), &B[(size_t)(lkB + r) * ldb + bn + lofB]);
    cp_commit();
    cp_wait<0>();
    __syncthreads();

    int buf = 0;
    for (int iter = 0; iter < NITER; iter++) {
        if (iter + 1 < NITER) {
            const int kt = (iter + 1) * BK;
            const int nb = buf ^ 1;
            #pragma unroll
            for (int r = 0; r < BK; r += 8)
                cp_async16(SA_ADDR(nb, lkA + r, lofA), &A[(size_t)(kt + lkA + r) * lda + bm + lofA]);
            #pragma unroll
            for (int r = 0; r < BK; r += 4)
                cp_async16(SB_ADDR(nb, lkB + r, lofB), &B[(size_t)(kt + lkB + r) * ldb + bn + lofB]);
            cp_commit();
        }

        // compute: ascending-k FFMA2 chains, lanes paired over M
        #pragma unroll
        for (int k = 0; k < BK; k++) {
            ulonglong2 av0 = *reinterpret_cast<const ulonglong2*>(&As[buf][k][ty]);
            ulonglong2 av1 = *reinterpret_cast<const ulonglong2*>(&As[buf][k][ty + 4]);
            float4 b0 = *reinterpret_cast<const float4*>(&Bs[buf][k][tx]);
            float4 b1 = *reinterpret_cast<const float4*>(&Bs[buf][k][tx + 64]);
            ull ap[4] = {av0.x, av0.y, av1.x, av1.y};
            ull bb[8];
            bb[0] = bcast2(b0.x); bb[1] = bcast2(b0.y);
            bb[2] = bcast2(b0.z); bb[3] = bcast2(b0.w);
            bb[4] = bcast2(b1.x); bb[5] = bcast2(b1.y);
            bb[6] = bcast2(b1.z); bb[7] = bcast2(b1.w);
            #pragma unroll
            for (int i = 0; i < 4; i++)
                #pragma unroll
                for (int j = 0; j < 8; j++)
                    ffma2(acc[i][j], ap[i], bb[j]);
        }

        if (iter + 1 < NITER) {
            cp_wait<0>();
            __syncthreads();
            buf ^= 1;
        }
    }

    // epilogue: m-pair i covers rows ty+2i, ty+2i+1
    if (addBias) {
        float4 bv0 = *reinterpret_cast<const float4*>(&bias[bn + tx]);
        float4 bv1 = *reinterpret_cast<const float4*>(&bias[bn + tx + 64]);
        const float bb[8] = {bv0.x, bv0.y, bv0.z, bv0.w, bv1.x, bv1.y, bv1.z, bv1.w};
        #pragma unroll
        for (int i = 0; i < 4; i++) {
            #pragma unroll
            for (int half = 0; half < 2; half++) {
                int row = bm + ty + 2 * i + half;
                float4 p0 = *reinterpret_cast<const float4*>(&C[(size_t)row * N + bn + tx]);
                float4 p1 = *reinterpret_cast<const float4*>(&C[(size_t)row * N + bn + tx + 64]);
                float pr[8] = {p0.x, p0.y, p0.z, p0.w, p1.x, p1.y, p1.z, p1.w};
                float o[8];
                #pragma unroll
                for (int j = 0; j < 8; j++) {
                    float lo, hi;
                    unpack2(lo, hi, acc[i][j]);
                    float mine = half ? hi : lo;
                    o[j] = __fadd_rn(__fadd_rn(pr[j], mine), bb[j]);
                }
                float4 s0 = {o[0], o[1], o[2], o[3]};
                float4 s1 = {o[4], o[5], o[6], o[7]};
                *reinterpret_cast<float4*>(&C[(size_t)row * N + bn + tx]) = s0;
                *reinterpret_cast<float4*>(&C[(size_t)row * N + bn + tx + 64]) = s1;
            }
        }
    } else {
        #pragma unroll
        for (int i = 0; i < 4; i++) {
            float lo[8], hi[8];
            #pragma unroll
            for (int j = 0; j < 8; j++) unpack2(lo[j], hi[j], acc[i][j]);
            int r0 = bm + ty + 2 * i;
            float4 s0 = {lo[0], lo[1], lo[2], lo[3]};
            float4 s1 = {lo[4], lo[5], lo[6], lo[7]};
            float4 s2 = {hi[0], hi[1], hi[2], hi[3]};
            float4 s3 = {hi[4], hi[5], hi[6], hi[7]};
            *reinterpret_cast<float4*>(&C[(size_t)r0 * N + bn + tx]) = s0;
            *reinterpret_cast<float4*>(&C[(size_t)r0 * N + bn + tx + 64]) = s1;
            *reinterpret_cast<float4*>(&C[(size_t)(r0 + 1) * N + bn + tx]) = s2;
            *reinterpret_cast<float4*>(&C[(size_t)(r0 + 1) * N + bn + tx + 64]) = s3;
        }
    }
    #undef SA_ADDR
    #undef SB_ADDR
}

// ---------------------------------------------------------------------------
// GEMM2 panel (R10-proven): 128x128 tile, 256 threads, 2 CTAs/SM, BK=32.
// A m-major (spk1) -> LDG-staged + STS; B k-major (w2T) -> cp.async.
// Same per-element numerics contract.
// ---------------------------------------------------------------------------
#define BM 128
#define BN 128

__global__ __launch_bounds__(256, 2)
void sgemm2_panel(const float* __restrict__ A,
                  const float* __restrict__ B,
                  const float* __restrict__ bias,
                  float* __restrict__ C,
                  int lda, int ldb, int N, int addBias)
{
    __shared__ __align__(16) float As[2][BK][BM];
    __shared__ __align__(16) float Bs[2][BK][BN];

    const int tid = threadIdx.x;
    const int bm = blockIdx.y * BM;
    const int bn = blockIdx.x * BN;

    const int tx = (tid & 15) << 2;   // n base (4 wide); second group at +64
    const int ty = (tid >> 4) << 2;   // m base (4 tall); second group at +64

    const int lk  = tid >> 5;          // 0..7
    const int lof = (tid & 31) << 2;   // 0..124

    const int lr  = tid >> 2;          // 0..63
    const int lc8 = (tid & 3) << 3;    // 0,8,16,24

    const uint32_t sB = (uint32_t)__cvta_generic_to_shared(&Bs[0][0][0]);
    #define SB2_ADDR(b, k, off) (sB + (uint32_t)(((b) * BK + (k)) * BN + (off)) * 4u)

    ull acc[4][8];
    #pragma unroll
    for (int i = 0; i < 4; i++)
        #pragma unroll
        for (int j = 0; j < 8; j++) acc[i][j] = 0ull;

    // prologue
    #pragma unroll
    for (int r = 0; r < BK; r += 8)
        cp_async16(SB2_ADDR(0, lk + r, lof), &B[(size_t)(lk + r) * ldb + bn + lof]);
    #pragma unroll
    for (int h = 0; h < 2; h++) {
        const int row = lr + h * 64;
        float4 a0 = *reinterpret_cast<const float4*>(&A[(size_t)(bm + row) * lda + lc8]);
        float4 a1 = *reinterpret_cast<const float4*>(&A[(size_t)(bm + row) * lda + lc8 + 4]);
        As[0][lc8 + 0][row] = a0.x; As[0][lc8 + 1][row] = a0.y;
        As[0][lc8 + 2][row] = a0.z; As[0][lc8 + 3][row] = a0.w;
        As[0][lc8 + 4][row] = a1.x; As[0][lc8 + 5][row] = a1.y;
        As[0][lc8 + 6][row] = a1.z; As[0][lc8 + 7][row] = a1.w;
    }
    cp_commit();
    cp_wait<0>();
    __syncthreads();

    int buf = 0;
    for (int iter = 0; iter < NITER; iter++) {
        float4 stA[4];
        if (iter + 1 < NITER) {
            const int kt = (iter + 1) * BK;
            const int nb = buf ^ 1;
            #pragma unroll
            for (int r = 0; r < BK; r += 8)
                cp_async16(SB2_ADDR(nb, lk + r, lof), &B[(size_t)(kt + lk + r) * ldb + bn + lof]);
            stA[0] = *reinterpret_cast<const float4*>(&A[(size_t)(bm + lr) * lda + kt + lc8]);
            stA[1] = *reinterpret_cast<const float4*>(&A[(size_t)(bm + lr) * lda + kt + lc8 + 4]);
            stA[2] = *reinterpret_cast<const float4*>(&A[(size_t)(bm + lr + 64) * lda + kt + lc8]);
            stA[3] = *reinterpret_cast<const float4*>(&A[(size_t)(bm + lr + 64) * lda + kt + lc8 + 4]);
            cp_commit();
        }

        #pragma unroll
        for (int k = 0; k < BK; k++) {
            ulonglong2 av0 = *reinterpret_cast<const ulonglong2*>(&As[buf][k][ty]);
            ulonglong2 av1 = *reinterpret_cast<const ulonglong2*>(&As[buf][k][ty + 64]);
            float4 b0 = *reinterpret_cast<const float4*>(&Bs[buf][k][tx]);
            float4 b1 = *reinterpret_cast<const float4*>(&Bs[buf][k][tx + 64]);
            ull ap[4] = {av0.x, av0.y, av1.x, av1.y};
            ull bb[8];
            bb[0] = bcast2(b0.x); bb[1] = bcast2(b0.y);
            bb[2] = bcast2(b0.z); bb[3] = bcast2(b0.w);
            bb[4] = bcast2(b1.x); bb[5] = bcast2(b1.y);
            bb[6] = bcast2(b1.z); bb[7] = bcast2(b1.w);
            #pragma unroll
            for (int i = 0; i < 4; i++)
                #pragma unroll
                for (int j = 0; j < 8; j++)
                    ffma2(acc[i][j], ap[i], bb[j]);
        }

        if (iter + 1 < NITER) {
            const int nb = buf ^ 1;
            const int row0 = lr, row1 = lr + 64;
            As[nb][lc8 + 0][row0] = stA[0].x; As[nb][lc8 + 1][row0] = stA[0].y;
            As[nb][lc8 + 2][row0] = stA[0].z; As[nb][lc8 + 3][row0] = stA[0].w;
            As[nb][lc8 + 4][row0] = stA[1].x; As[nb][lc8 + 5][row0] = stA[1].y;
            As[nb][lc8 + 6][row0] = stA[1].z; As[nb][lc8 + 7][row0] = stA[1].w;
            As[nb][lc8 + 0][row1] = stA[2].x; As[nb][lc8 + 1][row1] = stA[2].y;
            As[nb][lc8 + 2][row1] = stA[2].z; As[nb][lc8 + 3][row1] = stA[2].w;
            As[nb][lc8 + 4][row1] = stA[3].x; As[nb][lc8 + 5][row1] = stA[3].y;
            As[nb][lc8 + 6][row1] = stA[3].z; As[nb][lc8 + 7][row1] = stA[3].w;
            cp_wait<0>();
            __syncthreads();
            buf = nb;
        }
    }

    // epilogue
    if (addBias) {
        float4 bv0 = *reinterpret_cast<const float4*>(&bias[bn + tx]);
        float4 bv1 = *reinterpret_cast<const float4*>(&bias[bn + tx + 64]);
        const float bb[8] = {bv0.x, bv0.y, bv0.z, bv0.w, bv1.x, bv1.y, bv1.z, bv1.w};
        #pragma unroll
        for (int i = 0; i < 4; i++) {
            int r0 = bm + ((i < 2) ? (ty + 2 * i) : (ty + 64 + 2 * (i - 2)));
            #pragma unroll
            for (int half = 0; half < 2; half++) {
                int row = r0 + half;
                float4 p0 = *reinterpret_cast<const float4*>(&C[(size_t)row * N + bn + tx]);
                float4 p1 = *reinterpret_cast<const float4*>(&C[(size_t)row * N + bn + tx + 64]);
                float pr[8] = {p0.x, p0.y, p0.z, p0.w, p1.x, p1.y, p1.z, p1.w};
                float o[8];
                #pragma unroll
                for (int j = 0; j < 8; j++) {
                    float lo, hi;
                    unpack2(lo, hi, acc[i][j]);
                    float mine = half ? hi : lo;
                    o[j] = __fadd_rn(__fadd_rn(pr[j], mine), bb[j]);
                }
                float4 s0 = {o[0], o[1], o[2], o[3]};
                float4 s1 = {o[4], o[5], o[6], o[7]};
                *reinterpret_cast<float4*>(&C[(size_t)row * N + bn + tx]) = s0;
                *reinterpret_cast<float4*>(&C[(size_t)row * N + bn + tx + 64]) = s1;
            }
        }
    } else {
        #pragma unroll
        for (int i = 0; i < 4; i++) {
            int r0 = bm + ((i < 2) ? (ty + 2 * i) : (ty + 64 + 2 * (i - 2)));
            float lo[8], hi[8];
            #pragma unroll
            for (int j = 0; j < 8; j++) unpack2(lo[j], hi[j], acc[i][j]);
            float4 s0 = {lo[0], lo[1], lo[2], lo[3]};
            float4 s1 = {lo[4], lo[5], lo[6], lo[7]};
            float4 s2 = {hi[0], hi[1], hi[2], hi[3]};
            float4 s3 = {hi[4], hi[5], hi[6], hi[7]};
            *reinterpret_cast<float4*>(&C[(size_t)r0 * N + bn + tx]) = s0;
            *reinterpret_cast<float4*>(&C[(size_t)r0 * N + bn + tx + 64]) = s1;
            *reinterpret_cast<float4*>(&C[(size_t)(r0 + 1) * N + bn + tx]) = s2;
            *reinterpret_cast<float4*>(&C[(size_t)(r0 + 1) * N + bn + tx + 64]) = s3;
        }
    }
    #undef SB2_ADDR
}

// ---------------------------------------------------------------------------
// LIF recurrence, XLA-exact op ordering per lane (no FMA contraction).
// Scalar, one neuron per thread, next-t prefetch (R10-proven).
// ---------------------------------------------------------------------------
__device__ __forceinline__ void lif_step(float& mem, float& s, float c, float thr) {
    float t0 = __fmul_rn(BETA_F, mem);
    float t1 = __fadd_rn(t0, c);
    float t2 = __fmul_rn(s, thr);
    mem = __fsub_rn(t1, t2);
    s = (__fsub_rn(mem, thr) > 0.f) ? 1.0f : 0.0f;
}

__global__ void lif_scan1(const float* __restrict__ cur,
                          const float* __restrict__ thr_p,
                          float* __restrict__ spk_rec,
                          int stride)
{
    const int idx = blockIdx.x * blockDim.x + threadIdx.x;
    const float thr = *thr_p;
    float mem = 0.f, s = 0.f;
    const float* p = cur + idx;
    float* q = spk_rec + idx;
    float c = p[0];
    #pragma unroll 8
    for (int t = 0; t < T_STEPS; t++) {
        float cn = 0.f;
        if (t + 1 < T_STEPS) cn = p[(size_t)(t + 1) * stride];
        lif_step(mem, s, c, thr);
        q[(size_t)t * stride] = s;
        c = cn;
    }
}

// ---------------------------------------------------------------------------
extern "C" void kernel_launch(void* const* d_in, const int* in_sizes, int n_in,
                              void* d_out, int out_size)
{
    const float* x    = (const float*)d_in[0];  // [T,B,I]
    const float* w1   = (const float*)d_in[1];  // [H,I]
    const float* b1   = (const float*)d_in[2];  // [H]
    const float* w2   = (const float*)d_in[3];  // [O,H]
    const float* b2   = (const float*)d_in[4];  // [O]
    const float* thr1 = (const float*)d_in[5];  // scalar
    const float* thr2 = (const float*)d_in[6];  // scalar

    float* out  = (float*)d_out;
    float* spk1 = out;                                    // [T,B,H]
    float* spk2 = out + (size_t)T_STEPS * BATCH * HID;    // [T,B,O]

    float *cur1, *cur2, *xT, *w1T, *w2T;
    cudaGetSymbolAddress((void**)&cur1, g_cur1);
    cudaGetSymbolAddress((void**)&cur2, g_cur2);
    cudaGetSymbolAddress((void**)&xT,  g_xT);
    cudaGetSymbolAddress((void**)&w1T, g_w1T);
    cudaGetSymbolAddress((void**)&w2T, g_w2T);

    // prep: bit-copy transposes to k-major layouts (launch idx 0-2;
    // GEMM1 phase0 lands at idx 3 = the ncu capture slot)
    transpose32<<<dim3(INDIM / 32, MROWS / 32), dim3(32, 8)>>>(x, xT, MROWS, INDIM);
    transpose32<<<dim3(INDIM / 32, HID / 32), dim3(32, 8)>>>(w1, w1T, HID, INDIM);
    transpose32<<<dim3(HID / 32, OUTDIM / 32), dim3(32, 8)>>>(w2, w2T, OUTDIM, HID);

    // 1) cur1 = X @ W1^T + b1   (two kc=512 panels; 64x128 CTAs, 4/SM)
    {
        dim3 grid(HID / BN1, MROWS / BM1);   // (8, 512) = 4096 CTAs
        sgemm1_panel<<<grid, 128>>>(xT, w1T, b1, cur1, MROWS, HID, HID, 0);
        sgemm1_panel<<<grid, 128>>>(xT + (size_t)KC * MROWS, w1T + (size_t)KC * HID,
                                    b1, cur1, MROWS, HID, HID, 1);
    }
    // 2) LIF layer 1 -> spk1_rec
    lif_scan1<<<(BATCH * HID) / 256, 256>>>(cur1, thr1, spk1, BATCH * HID);

    // 3) cur2 = spk1_rec @ W2^T + b2   (R10-proven 128x128 split panels)
    {
        dim3 grid(OUTDIM / BN, MROWS / BM);  // (2, 256) = 512 CTAs
        sgemm2_panel<<<grid, 256>>>(spk1, w2T, b2, cur2, HID, OUTDIM, OUTDIM, 0);
        sgemm2_panel<<<grid, 256>>>(spk1 + KC, w2T + (size_t)KC * OUTDIM,
                                    b2, cur2, HID, OUTDIM, OUTDIM, 1);
    }
    // 4) LIF layer 2 -> spk2_rec
    lif_scan1<<<(BATCH * OUTDIM) / 256, 256>>>(cur2, thr2, spk2, BATCH * OUTDIM);
}

// round 14
// speedup vs baseline: 1.0756x; 1.0288x over previous
#include <cuda_runtime.h>
#include <cstdint>

// Problem dims
#define T_STEPS 256
#define BATCH   128
#define INDIM   1024
#define HID     1024
#define OUTDIM  256
#define MROWS   (T_STEPS * BATCH)   // 32768
#define BETA_F  0.9f
#define KC      512                 // Eigen gebp panel depth (bit-exactness contract)

// Scratch (allocation-free rule: __device__ globals)
__device__ float g_cur1[(size_t)MROWS * HID];     // 128 MB
__device__ float g_cur2[(size_t)MROWS * OUTDIM];  // 32 MB
__device__ float g_xT  [(size_t)INDIM * MROWS];   // 128 MB  x transposed (k-major)
__device__ float g_w1T [(size_t)INDIM * HID];     // 4 MB    w1 transposed
__device__ float g_w2T [(size_t)HID * OUTDIM];    // 1 MB    w2 transposed

typedef unsigned long long ull;

// ---- packed f32x2 helpers (each lane = independent IEEE fp32 rn op) --------
__device__ __forceinline__ void ffma2(ull& d, ull a, ull b) {
    asm("fma.rn.f32x2 %0, %1, %2, %0;" : "+l"(d) : "l"(a), "l"(b));
}
__device__ __forceinline__ ull bcast2(float x) {
    ull r; asm("mov.b64 %0, {%1, %1};" : "=l"(r) : "f"(x)); return r;
}
__device__ __forceinline__ void unpack2(float& lo, float& hi, ull v) {
    asm("mov.b64 {%0, %1}, %2;" : "=f"(lo), "=f"(hi) : "l"(v));
}

// ---- cp.async helpers ------------------------------------------------------
__device__ __forceinline__ void cp_async16(uint32_t smem, const void* g) {
    asm volatile("cp.async.cg.shared.global [%0], [%1], 16;" :: "r"(smem), "l"(g));
}
__device__ __forceinline__ void cp_commit() {
    asm volatile("cp.async.commit_group;" ::: "memory");
}
template<int N>
__device__ __forceinline__ void cp_wait() {
    asm volatile("cp.async.wait_group %0;" :: "n"(N) : "memory");
}

// ---------------------------------------------------------------------------
// Tiled transpose: in [rows][cols] -> out [cols][rows]. Pure bit copy.
// ---------------------------------------------------------------------------
__global__ void transpose32(const float* __restrict__ in, float* __restrict__ out,
                            int rows, int cols)
{
    __shared__ float tile[32][33];
    const int c0 = blockIdx.x * 32;
    const int r0 = blockIdx.y * 32;
    #pragma unroll
    for (int j = 0; j < 32; j += 8)
        tile[threadIdx.y + j][threadIdx.x] =
            in[(size_t)(r0 + threadIdx.y + j) * cols + c0 + threadIdx.x];
    __syncthreads();
    #pragma unroll
    for (int j = 0; j < 32; j += 8)
        out[(size_t)(c0 + threadIdx.y + j) * rows + r0 + threadIdx.x] =
            tile[threadIdx.x][threadIdx.y + j];
}

#define BK 32
#define NITER (KC / BK)   // 16
#define BM1 64
#define BN1 128

// ---------------------------------------------------------------------------
// GEMM1 panel (kc=512): A,B k-major, cp.async, 2-stage, BK=32.
// R13-PROVEN: 64x128 tile, 128 threads, 4 CTAs/SM (506.7us/phase, fma=85%).
// Numerics contract (bit-match Eigen gebp kc=512, VERIFIED rel_err==0):
//   per element: S = fadd( chain(k=0..511), chain(k=512..1023) ), chains are
//   ascending-k fp32 FMA chains from 0; then ONE rounded bias add (phase 1).
// Microtile 8m(4 f32x2 m-pairs) x 8n per thread.
// ---------------------------------------------------------------------------
__global__ __launch_bounds__(128, 4)
void sgemm1_panel(const float* __restrict__ A,
                  const float* __restrict__ B,
                  const float* __restrict__ bias,
                  float* __restrict__ C,
                  int lda, int ldb, int N, int addBias)
{
    __shared__ __align__(16) float As[2][BK][BM1];   // 16 KB
    __shared__ __align__(16) float Bs[2][BK][BN1];   // 32 KB

    const int tid = threadIdx.x;
    const int bm = blockIdx.y * BM1;
    const int bn = blockIdx.x * BN1;

    const int tx = (tid & 15) << 2;   // n base (4 wide); second group at +64
    const int ty = (tid >> 4) << 3;   // m base (8 tall, consecutive)

    const int lkA  = tid >> 4;          // 0..7
    const int lofA = (tid & 15) << 2;   // 0..60
    const int lkB  = tid >> 5;          // 0..3
    const int lofB = (tid & 31) << 2;   // 0..124

    const uint32_t sA = (uint32_t)__cvta_generic_to_shared(&As[0][0][0]);
    const uint32_t sB = (uint32_t)__cvta_generic_to_shared(&Bs[0][0][0]);
    #define SA_ADDR(b, k, off) (sA + (uint32_t)(((b) * BK + (k)) * BM1 + (off)) * 4u)
    #define SB_ADDR(b, k, off) (sB + (uint32_t)(((b) * BK + (k)) * BN1 + (off)) * 4u)

    ull acc[4][8];
    #pragma unroll
    for (int i = 0; i < 4; i++)
        #pragma unroll
        for (int j = 0; j < 8; j++) acc[i][j] = 0ull;

    // prologue
    #pragma unroll
    for (int r = 0; r < BK; r += 8)
        cp_async16(SA_ADDR(0, lkA + r, lofA), &A[(size_t)(lkA + r) * lda + bm + lofA]);
    #pragma unroll
    for (int r = 0; r < BK; r += 4)
        cp_async16(SB_ADDR(0, lkB + r, lofB), &B[(size_t)(lkB + r) * ldb + bn + lofB]);
    cp_commit();
    cp_wait<0>();
    __syncthreads();

    int buf = 0;
    for (int iter = 0; iter < NITER; iter++) {
        if (iter + 1 < NITER) {
            const int kt = (iter + 1) * BK;
            const int nb = buf ^ 1;
            #pragma unroll
            for (int r = 0; r < BK; r += 8)
                cp_async16(SA_ADDR(nb, lkA + r, lofA), &A[(size_t)(kt + lkA + r) * lda + bm + lofA]);
            #pragma unroll
            for (int r = 0; r < BK; r += 4)
                cp_async16(SB_ADDR(nb, lkB + r, lofB), &B[(size_t)(kt + lkB + r) * ldb + bn + lofB]);
            cp_commit();
        }

        #pragma unroll
        for (int k = 0; k < BK; k++) {
            ulonglong2 av0 = *reinterpret_cast<const ulonglong2*>(&As[buf][k][ty]);
            ulonglong2 av1 = *reinterpret_cast<const ulonglong2*>(&As[buf][k][ty + 4]);
            float4 b0 = *reinterpret_cast<const float4*>(&Bs[buf][k][tx]);
            float4 b1 = *reinterpret_cast<const float4*>(&Bs[buf][k][tx + 64]);
            ull ap[4] = {av0.x, av0.y, av1.x, av1.y};
            ull bb[8];
            bb[0] = bcast2(b0.x); bb[1] = bcast2(b0.y);
            bb[2] = bcast2(b0.z); bb[3] = bcast2(b0.w);
            bb[4] = bcast2(b1.x); bb[5] = bcast2(b1.y);
            bb[6] = bcast2(b1.z); bb[7] = bcast2(b1.w);
            #pragma unroll
            for (int i = 0; i < 4; i++)
                #pragma unroll
                for (int j = 0; j < 8; j++)
                    ffma2(acc[i][j], ap[i], bb[j]);
        }

        if (iter + 1 < NITER) {
            cp_wait<0>();
            __syncthreads();
            buf ^= 1;
        }
    }

    // epilogue
    if (addBias) {
        float4 bv0 = *reinterpret_cast<const float4*>(&bias[bn + tx]);
        float4 bv1 = *reinterpret_cast<const float4*>(&bias[bn + tx + 64]);
        const float bb[8] = {bv0.x, bv0.y, bv0.z, bv0.w, bv1.x, bv1.y, bv1.z, bv1.w};
        #pragma unroll
        for (int i = 0; i < 4; i++) {
            #pragma unroll
            for (int half = 0; half < 2; half++) {
                int row = bm + ty + 2 * i + half;
                float4 p0 = *reinterpret_cast<const float4*>(&C[(size_t)row * N + bn + tx]);
                float4 p1 = *reinterpret_cast<const float4*>(&C[(size_t)row * N + bn + tx + 64]);
                float pr[8] = {p0.x, p0.y, p0.z, p0.w, p1.x, p1.y, p1.z, p1.w};
                float o[8];
                #pragma unroll
                for (int j = 0; j < 8; j++) {
                    float lo, hi;
                    unpack2(lo, hi, acc[i][j]);
                    float mine = half ? hi : lo;
                    o[j] = __fadd_rn(__fadd_rn(pr[j], mine), bb[j]);
                }
                float4 s0 = {o[0], o[1], o[2], o[3]};
                float4 s1 = {o[4], o[5], o[6], o[7]};
                *reinterpret_cast<float4*>(&C[(size_t)row * N + bn + tx]) = s0;
                *reinterpret_cast<float4*>(&C[(size_t)row * N + bn + tx + 64]) = s1;
            }
        }
    } else {
        #pragma unroll
        for (int i = 0; i < 4; i++) {
            float lo[8], hi[8];
            #pragma unroll
            for (int j = 0; j < 8; j++) unpack2(lo[j], hi[j], acc[i][j]);
            int r0 = bm + ty + 2 * i;
            float4 s0 = {lo[0], lo[1], lo[2], lo[3]};
            float4 s1 = {lo[4], lo[5], lo[6], lo[7]};
            float4 s2 = {hi[0], hi[1], hi[2], hi[3]};
            float4 s3 = {hi[4], hi[5], hi[6], hi[7]};
            *reinterpret_cast<float4*>(&C[(size_t)r0 * N + bn + tx]) = s0;
            *reinterpret_cast<float4*>(&C[(size_t)r0 * N + bn + tx + 64]) = s1;
            *reinterpret_cast<float4*>(&C[(size_t)(r0 + 1) * N + bn + tx]) = s2;
            *reinterpret_cast<float4*>(&C[(size_t)(r0 + 1) * N + bn + tx + 64]) = s3;
        }
    }
    #undef SA_ADDR
    #undef SB_ADDR
}

// ---------------------------------------------------------------------------
// GEMM2 panel, NEW R13-shape: 64x128 tile, 128 threads, 4 CTAs/SM.
// A m-major (spk1): thread stages row (tid>>1), k-cols ((tid&1)*16..+15)
// (4 float4 LDG) and STS-transposes into As[k][row]. B k-major via cp.async.
// Same per-element numerics contract. Microtile 8m(4 m-pairs) x 8n.
// Grid (2,512)=1024 CTAs -> ~86% last-wave fill at occ 4.
// ---------------------------------------------------------------------------
__global__ __launch_bounds__(128, 4)
void sgemm2_panel(const float* __restrict__ A,
                  const float* __restrict__ B,
                  const float* __restrict__ bias,
                  float* __restrict__ C,
                  int lda, int ldb, int N, int addBias)
{
    __shared__ __align__(16) float As[2][BK][BM1];   // 16 KB
    __shared__ __align__(16) float Bs[2][BK][BN1];   // 32 KB

    const int tid = threadIdx.x;
    const int bm = blockIdx.y * BM1;
    const int bn = blockIdx.x * BN1;

    const int tx = (tid & 15) << 2;
    const int ty = (tid >> 4) << 3;

    const int lkB  = tid >> 5;          // 0..3
    const int lofB = (tid & 31) << 2;   // 0..124

    // A staging: row lr2 (0..63), 16 k-cols starting at lc16 (0 or 16)
    const int lr2  = tid >> 1;          // 0..63
    const int lc16 = (tid & 1) << 4;    // 0, 16

    const uint32_t sB = (uint32_t)__cvta_generic_to_shared(&Bs[0][0][0]);
    #define SB2_ADDR(b, k, off) (sB + (uint32_t)(((b) * BK + (k)) * BN1 + (off)) * 4u)

    ull acc[4][8];
    #pragma unroll
    for (int i = 0; i < 4; i++)
        #pragma unroll
        for (int j = 0; j < 8; j++) acc[i][j] = 0ull;

    // prologue
    #pragma unroll
    for (int r = 0; r < BK; r += 4)
        cp_async16(SB2_ADDR(0, lkB + r, lofB), &B[(size_t)(lkB + r) * ldb + bn + lofB]);
    {
        #pragma unroll
        for (int q = 0; q < 4; q++) {
            float4 a = *reinterpret_cast<const float4*>(&A[(size_t)(bm + lr2) * lda + lc16 + 4 * q]);
            As[0][lc16 + 4 * q + 0][lr2] = a.x;
            As[0][lc16 + 4 * q + 1][lr2] = a.y;
            As[0][lc16 + 4 * q + 2][lr2] = a.z;
            As[0][lc16 + 4 * q + 3][lr2] = a.w;
        }
    }
    cp_commit();
    cp_wait<0>();
    __syncthreads();

    int buf = 0;
    for (int iter = 0; iter < NITER; iter++) {
        float4 stA[4];
        if (iter + 1 < NITER) {
            const int kt = (iter + 1) * BK;
            const int nb = buf ^ 1;
            #pragma unroll
            for (int r = 0; r < BK; r += 4)
                cp_async16(SB2_ADDR(nb, lkB + r, lofB), &B[(size_t)(kt + lkB + r) * ldb + bn + lofB]);
            #pragma unroll
            for (int q = 0; q < 4; q++)
                stA[q] = *reinterpret_cast<const float4*>(&A[(size_t)(bm + lr2) * lda + kt + lc16 + 4 * q]);
            cp_commit();
        }

        #pragma unroll
        for (int k = 0; k < BK; k++) {
            ulonglong2 av0 = *reinterpret_cast<const ulonglong2*>(&As[buf][k][ty]);
            ulonglong2 av1 = *reinterpret_cast<const ulonglong2*>(&As[buf][k][ty + 4]);
            float4 b0 = *reinterpret_cast<const float4*>(&Bs[buf][k][tx]);
            float4 b1 = *reinterpret_cast<const float4*>(&Bs[buf][k][tx + 64]);
            ull ap[4] = {av0.x, av0.y, av1.x, av1.y};
            ull bb[8];
            bb[0] = bcast2(b0.x); bb[1] = bcast2(b0.y);
            bb[2] = bcast2(b0.z); bb[3] = bcast2(b0.w);
            bb[4] = bcast2(b1.x); bb[5] = bcast2(b1.y);
            bb[6] = bcast2(b1.z); bb[7] = bcast2(b1.w);
            #pragma unroll
            for (int i = 0; i < 4; i++)
                #pragma unroll
                for (int j = 0; j < 8; j++)
                    ffma2(acc[i][j], ap[i], bb[j]);
        }

        if (iter + 1 < NITER) {
            const int nb = buf ^ 1;
            #pragma unroll
            for (int q = 0; q < 4; q++) {
                As[nb][lc16 + 4 * q + 0][lr2] = stA[q].x;
                As[nb][lc16 + 4 * q + 1][lr2] = stA[q].y;
                As[nb][lc16 + 4 * q + 2][lr2] = stA[q].z;
                As[nb][lc16 + 4 * q + 3][lr2] = stA[q].w;
            }
            cp_wait<0>();
            __syncthreads();
            buf = nb;
        }
    }

    // epilogue
    if (addBias) {
        float4 bv0 = *reinterpret_cast<const float4*>(&bias[bn + tx]);
        float4 bv1 = *reinterpret_cast<const float4*>(&bias[bn + tx + 64]);
        const float bb[8] = {bv0.x, bv0.y, bv0.z, bv0.w, bv1.x, bv1.y, bv1.z, bv1.w};
        #pragma unroll
        for (int i = 0; i < 4; i++) {
            #pragma unroll
            for (int half = 0; half < 2; half++) {
                int row = bm + ty + 2 * i + half;
                float4 p0 = *reinterpret_cast<const float4*>(&C[(size_t)row * N + bn + tx]);
                float4 p1 = *reinterpret_cast<const float4*>(&C[(size_t)row * N + bn + tx + 64]);
                float pr[8] = {p0.x, p0.y, p0.z, p0.w, p1.x, p1.y, p1.z, p1.w};
                float o[8];
                #pragma unroll
                for (int j = 0; j < 8; j++) {
                    float lo, hi;
                    unpack2(lo, hi, acc[i][j]);
                    float mine = half ? hi : lo;
                    o[j] = __fadd_rn(__fadd_rn(pr[j], mine), bb[j]);
                }
                float4 s0 = {o[0], o[1], o[2], o[3]};
                float4 s1 = {o[4], o[5], o[6], o[7]};
                *reinterpret_cast<float4*>(&C[(size_t)row * N + bn + tx]) = s0;
                *reinterpret_cast<float4*>(&C[(size_t)row * N + bn + tx + 64]) = s1;
            }
        }
    } else {
        #pragma unroll
        for (int i = 0; i < 4; i++) {
            float lo[8], hi[8];
            #pragma unroll
            for (int j = 0; j < 8; j++) unpack2(lo[j], hi[j], acc[i][j]);
            int r0 = bm + ty + 2 * i;
            float4 s0 = {lo[0], lo[1], lo[2], lo[3]};
            float4 s1 = {lo[4], lo[5], lo[6], lo[7]};
            float4 s2 = {hi[0], hi[1], hi[2], hi[3]};
            float4 s3 = {hi[4], hi[5], hi[6], hi[7]};
            *reinterpret_cast<float4*>(&C[(size_t)r0 * N + bn + tx]) = s0;
            *reinterpret_cast<float4*>(&C[(size_t)r0 * N + bn + tx + 64]) = s1;
            *reinterpret_cast<float4*>(&C[(size_t)(r0 + 1) * N + bn + tx]) = s2;
            *reinterpret_cast<float4*>(&C[(size_t)(r0 + 1) * N + bn + tx + 64]) = s3;
        }
    }
    #undef SB2_ADDR
}

// ---------------------------------------------------------------------------
// LIF recurrence, XLA-exact op ordering per lane (no FMA contraction).
// Scalar, one neuron per thread, next-t prefetch (R10-proven).
// ---------------------------------------------------------------------------
__device__ __forceinline__ void lif_step(float& mem, float& s, float c, float thr) {
    float t0 = __fmul_rn(BETA_F, mem);
    float t1 = __fadd_rn(t0, c);
    float t2 = __fmul_rn(s, thr);
    mem = __fsub_rn(t1, t2);
    s = (__fsub_rn(mem, thr) > 0.f) ? 1.0f : 0.0f;
}

__global__ void lif_scan1(const float* __restrict__ cur,
                          const float* __restrict__ thr_p,
                          float* __restrict__ spk_rec,
                          int stride)
{
    const int idx = blockIdx.x * blockDim.x + threadIdx.x;
    const float thr = *thr_p;
    float mem = 0.f, s = 0.f;
    const float* p = cur + idx;
    float* q = spk_rec + idx;
    float c = p[0];
    #pragma unroll 8
    for (int t = 0; t < T_STEPS; t++) {
        float cn = 0.f;
        if (t + 1 < T_STEPS) cn = p[(size_t)(t + 1) * stride];
        lif_step(mem, s, c, thr);
        q[(size_t)t * stride] = s;
        c = cn;
    }
}

// ---------------------------------------------------------------------------
extern "C" void kernel_launch(void* const* d_in, const int* in_sizes, int n_in,
                              void* d_out, int out_size)
{
    const float* x    = (const float*)d_in[0];  // [T,B,I]
    const float* w1   = (const float*)d_in[1];  // [H,I]
    const float* b1   = (const float*)d_in[2];  // [H]
    const float* w2   = (const float*)d_in[3];  // [O,H]
    const float* b2   = (const float*)d_in[4];  // [O]
    const float* thr1 = (const float*)d_in[5];  // scalar
    const float* thr2 = (const float*)d_in[6];  // scalar

    float* out  = (float*)d_out;
    float* spk1 = out;                                    // [T,B,H]
    float* spk2 = out + (size_t)T_STEPS * BATCH * HID;    // [T,B,O]

    float *cur1, *cur2, *xT, *w1T, *w2T;
    cudaGetSymbolAddress((void**)&cur1, g_cur1);
    cudaGetSymbolAddress((void**)&cur2, g_cur2);
    cudaGetSymbolAddress((void**)&xT,  g_xT);
    cudaGetSymbolAddress((void**)&w1T, g_w1T);
    cudaGetSymbolAddress((void**)&w2T, g_w2T);

    // prep: bit-copy transposes to k-major layouts (launch idx 0-2;
    // GEMM1 phase0 lands at idx 3 = the ncu capture slot)
    transpose32<<<dim3(INDIM / 32, MROWS / 32), dim3(32, 8)>>>(x, xT, MROWS, INDIM);
    transpose32<<<dim3(INDIM / 32, HID / 32), dim3(32, 8)>>>(w1, w1T, HID, INDIM);
    transpose32<<<dim3(HID / 32, OUTDIM / 32), dim3(32, 8)>>>(w2, w2T, OUTDIM, HID);

    // 1) cur1 = X @ W1^T + b1   (two kc=512 panels; 64x128 CTAs, 4/SM)
    {
        dim3 grid(HID / BN1, MROWS / BM1);   // (8, 512) = 4096 CTAs
        sgemm1_panel<<<grid, 128>>>(xT, w1T, b1, cur1, MROWS, HID, HID, 0);
        sgemm1_panel<<<grid, 128>>>(xT + (size_t)KC * MROWS, w1T + (size_t)KC * HID,
                                    b1, cur1, MROWS, HID, HID, 1);
    }
    // 2) LIF layer 1 -> spk1_rec
    lif_scan1<<<(BATCH * HID) / 256, 256>>>(cur1, thr1, spk1, BATCH * HID);

    // 3) cur2 = spk1_rec @ W2^T + b2   (64x128 CTAs, 4/SM, 1024 CTAs)
    {
        dim3 grid(OUTDIM / BN1, MROWS / BM1);  // (2, 512) = 1024 CTAs
        sgemm2_panel<<<grid, 128>>>(spk1, w2T, b2, cur2, HID, OUTDIM, OUTDIM, 0);
        sgemm2_panel<<<grid, 128>>>(spk1 + KC, w2T + (size_t)KC * OUTDIM,
                                    b2, cur2, HID, OUTDIM, OUTDIM, 1);
    }
    // 4) LIF layer 2 -> spk2_rec
    lif_scan1<<<(BATCH * OUTDIM) / 256, 256>>>(cur2, thr2, spk2, BATCH * OUTDIM);
}